// round 2
// baseline (speedup 1.0000x reference)
#include <cuda_runtime.h>

#define VOCAB 512
#define EMBD  128
#define HID   64
#define BATCH 256
#define TLEN  1024

// Precomputed layer-0 input table: P0[v][j] = bih0[j] + bhh0[j] + emb[v] . Wih0[j]
__device__ float g_P0[VOCAB * HID];

// ---------------------------------------------------------------------------
// Kernel 1: precompute P0 (512 x 64, each a 128-dot). Trivial cost.
// ---------------------------------------------------------------------------
__global__ void precompute_P0(const float* __restrict__ emb,
                              const float* __restrict__ Wih0,
                              const float* __restrict__ bih0,
                              const float* __restrict__ bhh0)
{
    __shared__ float embs[EMBD];
    __shared__ float ws[HID * (EMBD + 1)];   // padded stride 129 -> conflict-free
    const int v = blockIdx.x;
    const int j = threadIdx.x;               // 64 threads

    embs[j]      = emb[v * EMBD + j];
    embs[j + 64] = emb[v * EMBD + j + 64];
    for (int r = 0; r < HID; r++) {
        ws[r * (EMBD + 1) + j]      = Wih0[r * EMBD + j];
        ws[r * (EMBD + 1) + j + 64] = Wih0[r * EMBD + j + 64];
    }
    __syncthreads();

    float acc = bih0[j] + bhh0[j];
    #pragma unroll
    for (int k = 0; k < EMBD; k++)
        acc += embs[k] * ws[j * (EMBD + 1) + k];
    g_P0[v * HID + j] = acc;
}

// ---------------------------------------------------------------------------
// Kernel 2: the fused 2-layer RNN scan + head.
//
// Grid: 128 CTAs x 256 threads. CTA owns 2 batch elements (group g = tid/128).
// Per batch, 128 threads: r = tid & 127, u = r>>1 (hidden unit), half = r&1.
//   L0 part: thread computes half of Whh0[u] . h0_old  (32 MACs, weights in regs)
//   L1 part: even computes Wih1[u] . h0[p-1], odd computes Whh1[u] . h1[p-2]
//            (64 MACs each, weights in regs)
// Pipelined: phase p produces h0[p] and h1[p-1]; ONE __syncthreads per phase.
// ---------------------------------------------------------------------------
__global__ __launch_bounds__(256, 1)
void rnn_scan_kernel(const int*   __restrict__ x,
                     const float* __restrict__ Whh0,
                     const float* __restrict__ Wih1,
                     const float* __restrict__ Whh1,
                     const float* __restrict__ bih1,
                     const float* __restrict__ bhh1,
                     const float* __restrict__ W1,
                     const float* __restrict__ b1,
                     const float* __restrict__ W2,
                     const float* __restrict__ b2,
                     float*       __restrict__ out)
{
    extern __shared__ float smem[];
    // layout: P0s[VOCAB*HID] | xs[2*TLEN] (int) | hbuf[512]
    float* P0s  = smem;
    int*   xs   = (int*)(smem + VOCAB * HID);
    float* hbuf = smem + VOCAB * HID + 2 * TLEN;
    // hbuf: [0..127]=h0 buf0 (g0,g1) [128..255]=h0 buf1 [256..383]=h1 buf0 [384..511]=h1 buf1

    const int tid  = threadIdx.x;
    const int g    = tid >> 7;       // batch group within CTA
    const int r    = tid & 127;
    const int u    = r >> 1;         // hidden unit
    const int half = r & 1;
    const int bidx = blockIdx.x * 2 + g;

    // Stage P0 table, token rows; zero h buffers.
    for (int i = tid; i < VOCAB * HID; i += 256) P0s[i] = g_P0[i];
    for (int i = tid; i < 2 * TLEN; i += 256) {
        int bb = blockIdx.x * 2 + (i / TLEN);
        xs[i] = x[bb * TLEN + (i % TLEN)];
    }
    for (int i = tid; i < 512; i += 256) hbuf[i] = 0.0f;

    // Weight registers.
    float w0[32];
    #pragma unroll
    for (int i = 0; i < 32; i++) w0[i] = Whh0[u * HID + half * 32 + i];
    float w1[64];
    const float* Wl1 = half ? Whh1 : Wih1;
    #pragma unroll
    for (int i = 0; i < 64; i++) w1[i] = Wl1[u * HID + i];
    const float c1 = bih1[u] + bhh1[u];

    __syncthreads();

    float* h0b0 = hbuf +   0 + g * 64;
    float* h0b1 = hbuf + 128 + g * 64;
    float* h1b0 = hbuf + 256 + g * 64;
    float* h1b1 = hbuf + 384 + g * 64;

    for (int p = 0; p <= TLEN; p++) {
        const int rb = p & 1;
        const float4* h0old = (const float4*)(rb ? h0b1 : h0b0);
        const float4* h1old = (const float4*)(rb ? h1b1 : h1b0);
        float*        h0w   = rb ? h0b0 : h0b1;
        float*        h1w   = rb ? h1b0 : h1b1;

        // ---- layer-0 partial: (my 32-k half of) Whh0[u] . h0[p-1]
        float a0 = 0.f, a1 = 0.f, a2 = 0.f, a3 = 0.f;
        #pragma unroll
        for (int jj = 0; jj < 8; jj++) {
            float4 hv = h0old[half * 8 + jj];
            a0 += hv.x * w0[jj * 4 + 0];
            a1 += hv.y * w0[jj * 4 + 1];
            a2 += hv.z * w0[jj * 4 + 2];
            a3 += hv.w * w0[jj * 4 + 3];
        }
        float pl0 = (a0 + a1) + (a2 + a3);

        // ---- layer-1 partial: even = Wih1[u] . h0[p-1], odd = Whh1[u] . h1[p-2]
        const float4* src = half ? h1old : h0old;
        float c0 = 0.f, c1a = 0.f, c2 = 0.f, c3 = 0.f;
        #pragma unroll
        for (int jj = 0; jj < 16; jj++) {
            float4 hv = src[jj];
            c0  += hv.x * w1[jj * 4 + 0];
            c1a += hv.y * w1[jj * 4 + 1];
            c2  += hv.z * w1[jj * 4 + 2];
            c3  += hv.w * w1[jj * 4 + 3];
        }
        float pl1 = (c0 + c1a) + (c2 + c3);

        // ---- pair-combine (lanes 2u, 2u+1)
        float o0 = pl0 + __shfl_xor_sync(0xffffffffu, pl0, 1);
        float o1 = pl1 + __shfl_xor_sync(0xffffffffu, pl1, 1);

        if (half == 0) {
            // finalize h0[p]
            int tt  = (p < TLEN) ? p : (TLEN - 1);
            int tok = xs[g * TLEN + tt];
            h0w[u] = tanhf(o0 + P0s[tok * HID + u]);
        } else {
            // finalize h1[p-1]   (p==0 seeds h1[-1] = 0)
            h0w = h0w; // no-op to keep symmetric structure
            h1w[u] = (p == 0) ? 0.0f : tanhf(o1 + c1);
        }
        __syncthreads();
    }

    // Final hidden h1[T-1] lives in the buffer written at phase T.
    const float* h1f = ((TLEN & 1) ? h1b0 : h1b1);

    // ---- head: y = relu(h1f @ W1^T + b1) @ W2^T + b2   (lanes 0..31 per group)
    if (r < 32) {
        const int i = r;
        float acc = b1[i];
        #pragma unroll
        for (int k = 0; k < HID; k++)
            acc += W1[i * HID + k] * h1f[k];
        acc = fmaxf(acc, 0.0f);
        float s = acc * W2[i];
        #pragma unroll
        for (int off = 16; off; off >>= 1)
            s += __shfl_down_sync(0xffffffffu, s, off);
        if (i == 0) out[bidx] = s + b2[0];
    }
}

// ---------------------------------------------------------------------------
extern "C" void kernel_launch(void* const* d_in, const int* in_sizes, int n_in,
                              void* d_out, int out_size)
{
    const int*   x    = (const int*)  d_in[0];
    const float* emb  = (const float*)d_in[1];
    const float* Wih0 = (const float*)d_in[2];
    const float* Whh0 = (const float*)d_in[3];
    const float* bih0 = (const float*)d_in[4];
    const float* bhh0 = (const float*)d_in[5];
    const float* Wih1 = (const float*)d_in[6];
    const float* Whh1 = (const float*)d_in[7];
    const float* bih1 = (const float*)d_in[8];
    const float* bhh1 = (const float*)d_in[9];
    const float* W1   = (const float*)d_in[10];
    const float* b1   = (const float*)d_in[11];
    const float* W2   = (const float*)d_in[12];
    const float* b2   = (const float*)d_in[13];
    float* out = (float*)d_out;

    precompute_P0<<<VOCAB, 64>>>(emb, Wih0, bih0, bhh0);

    const int smem_bytes = (VOCAB * HID + 2 * TLEN + 512) * 4;  // 141,312 B
    cudaFuncSetAttribute(rnn_scan_kernel,
                         cudaFuncAttributeMaxDynamicSharedMemorySize, smem_bytes);
    rnn_scan_kernel<<<BATCH / 2, 256, smem_bytes>>>(
        x, Whh0, Wih1, Whh1, bih1, bhh1, W1, b1, W2, b2, out);
}

// round 3
// speedup vs baseline: 2.3057x; 2.3057x over previous
#include <cuda_runtime.h>
#include <cstring>

#define VOCAB 512
#define EMBD  128
#define HID   64
#define BATCH 256
#define TLEN  1024

// Precomputed layer-0 input table: P0[v][j] = bih0[j] + bhh0[j] + emb[v] . Wih0[j]
__device__ float g_P0[VOCAB * HID];

// ---------------------------------------------------------------------------
// Kernel 1: precompute P0 (512 x 64, each a 128-dot). Trivial cost.
// ---------------------------------------------------------------------------
__global__ void precompute_P0(const float* __restrict__ emb,
                              const float* __restrict__ Wih0,
                              const float* __restrict__ bih0,
                              const float* __restrict__ bhh0)
{
    __shared__ float embs[EMBD];
    __shared__ float ws[HID * (EMBD + 1)];
    const int v = blockIdx.x;
    const int j = threadIdx.x;               // 64 threads

    embs[j]      = emb[v * EMBD + j];
    embs[j + 64] = emb[v * EMBD + j + 64];
    for (int r = 0; r < HID; r++) {
        ws[r * (EMBD + 1) + j]      = Wih0[r * EMBD + j];
        ws[r * (EMBD + 1) + j + 64] = Wih0[r * EMBD + j + 64];
    }
    __syncthreads();

    float acc = bih0[j] + bhh0[j];
    #pragma unroll
    for (int k = 0; k < EMBD; k++)
        acc += embs[k] * ws[j * (EMBD + 1) + k];
    g_P0[v * HID + j] = acc;
}

// ---------------------------------------------------------------------------
// Packed-f32x2 FMA (Blackwell FFMA2 — only reachable via PTX fma.rn.f32x2)
// ---------------------------------------------------------------------------
__device__ __forceinline__ void ffma2(unsigned long long& d,
                                      unsigned long long a,
                                      unsigned long long b)
{
    asm("fma.rn.f32x2 %0, %1, %2, %0;" : "+l"(d) : "l"(a), "l"(b));
}

__device__ __forceinline__ float hsum2(unsigned long long a)
{
    float2 f;
    memcpy(&f, &a, 8);
    return f.x + f.y;
}

__device__ __forceinline__ float tanh_fast(float x)
{
    float y;
    asm("tanh.approx.f32 %0, %1;" : "=f"(y) : "f"(x));
    return y;
}

// ---------------------------------------------------------------------------
// Kernel 2: fused 2-layer RNN scan + head.
//
// Grid: 128 CTAs x 128 threads. CTA owns 2 batches (group g = tid>>6, 64
// threads each, i.e. warps {0,1} / {2,3} -> one warp per SMSP).
// Thread u of a group owns hidden unit u for BOTH layers:
//   h0_new[u] = tanh(P0[tok] [u] + Whh0[u].h0_old)          (64 MAC)
//   h1_new[u] = tanh(Wih1[u].h0_old + Whh1[u].h1_old + c1)  (128 MAC)
// All 192 MACs as 96 packed fma.rn.f32x2 with weights register-resident.
// No shuffles. One 2-warp named barrier per phase (bar.sync 1+g, 64).
// Layers software-pipelined: phase p makes h0[p] and h1[p-1].
// ---------------------------------------------------------------------------
__global__ __launch_bounds__(128, 1)
void rnn_scan_kernel(const int*   __restrict__ x,
                     const float* __restrict__ Whh0,
                     const float* __restrict__ Wih1,
                     const float* __restrict__ Whh1,
                     const float* __restrict__ bih1,
                     const float* __restrict__ bhh1,
                     const float* __restrict__ W1,
                     const float* __restrict__ b1,
                     const float* __restrict__ W2,
                     const float* __restrict__ b2,
                     float*       __restrict__ out)
{
    extern __shared__ float smem[];
    // layout: P0s[VOCAB*HID] | xs[2*TLEN] (int) | hbuf[512]
    float* P0s  = smem;
    int*   xs   = (int*)(smem + VOCAB * HID);
    float* hbuf = smem + VOCAB * HID + 2 * TLEN;

    const int tid  = threadIdx.x;
    const int g    = tid >> 6;       // batch group within CTA
    const int u    = tid & 63;       // hidden unit
    const int bidx = blockIdx.x * 2 + g;

    // ---- stage P0 table (float4), token rows; zero h buffers
    {
        const float4* srcp = (const float4*)g_P0;
        float4*       dstp = (float4*)P0s;
        for (int i = tid; i < (VOCAB * HID) / 4; i += 128) dstp[i] = srcp[i];
    }
    for (int i = tid; i < 2 * TLEN; i += 128)
        xs[i] = x[(blockIdx.x * 2 + (i >> 10)) * TLEN + (i & (TLEN - 1))];
    for (int i = tid; i < 512; i += 128) hbuf[i] = 0.0f;

    // ---- pack weights into 64-bit f32x2 registers (96 u64 = 192 floats)
    unsigned long long w0p[32], w1p[32], w2p[32];
    {
        const unsigned long long* a = (const unsigned long long*)(Whh0 + u * HID);
        const unsigned long long* bq = (const unsigned long long*)(Wih1 + u * HID);
        const unsigned long long* c = (const unsigned long long*)(Whh1 + u * HID);
        #pragma unroll
        for (int k = 0; k < 32; k++) { w0p[k] = a[k]; w1p[k] = bq[k]; w2p[k] = c[k]; }
    }
    const float c1 = bih1[u] + bhh1[u];

    __syncthreads();

    float* base = hbuf + g * 256;
    float* h0b0 = base;        // h0 buffer 0
    float* h0b1 = base + 64;   // h0 buffer 1
    float* h1b0 = base + 128;  // h1 buffer 0
    float* h1b1 = base + 192;  // h1 buffer 1
    const int barid = 1 + g;

    for (int p = 0; p <= TLEN; p++) {
        const int rb = p & 1;
        const ulonglong2* h0old = (const ulonglong2*)(rb ? h0b1 : h0b0);
        const ulonglong2* h1old = (const ulonglong2*)(rb ? h1b1 : h1b0);
        float*            h0w   = rb ? h0b0 : h0b1;
        float*            h1w   = rb ? h1b0 : h1b1;

        // token / P0 lookup early (hide the dependent LDS->LDS chain)
        const int   tt  = (p < TLEN) ? p : (TLEN - 1);
        const int   tok = xs[g * TLEN + tt];
        const float p0v = P0s[tok * HID + u];

        unsigned long long a0 = 0, a1 = 0, b0a = 0, b1a = 0, c0 = 0, c1a = 0;
        #pragma unroll
        for (int jj = 0; jj < 16; jj++) {
            ulonglong2 hv = h0old[jj];          // 4 floats of h0_old (shared, broadcast)
            ffma2(a0,  hv.x, w0p[2 * jj]);      // L0:  Whh0[u] . h0_old
            ffma2(a1,  hv.y, w0p[2 * jj + 1]);
            ffma2(b0a, hv.x, w1p[2 * jj]);      // L1a: Wih1[u] . h0_old
            ffma2(b1a, hv.y, w1p[2 * jj + 1]);
            ulonglong2 gv = h1old[jj];          // 4 floats of h1_old
            ffma2(c0,  gv.x, w2p[2 * jj]);      // L1b: Whh1[u] . h1_old
            ffma2(c1a, gv.y, w2p[2 * jj + 1]);
        }
        const float s0 = hsum2(a0) + hsum2(a1);
        const float s1 = (hsum2(b0a) + hsum2(b1a)) + (hsum2(c0) + hsum2(c1a));

        h0w[u] = tanh_fast(s0 + p0v);
        h1w[u] = (p == 0) ? 0.0f : tanh_fast(s1 + c1);

        asm volatile("bar.sync %0, 64;" :: "r"(barid) : "memory");
    }

    // phase p=TLEN (rb=0) wrote h1[T-1] into h1b1
    const float* h1f = h1b1;

    // ---- head: y = relu(h1f @ W1^T + b1) @ W2^T + b2  (first warp of group)
    if (u < 32) {
        float acc = b1[u];
        #pragma unroll
        for (int k = 0; k < HID; k++)
            acc += W1[u * HID + k] * h1f[k];
        acc = fmaxf(acc, 0.0f);
        float s = acc * W2[u];
        #pragma unroll
        for (int off = 16; off; off >>= 1)
            s += __shfl_down_sync(0xffffffffu, s, off);
        if (u == 0) out[bidx] = s + b2[0];
    }
}

// ---------------------------------------------------------------------------
extern "C" void kernel_launch(void* const* d_in, const int* in_sizes, int n_in,
                              void* d_out, int out_size)
{
    const int*   x    = (const int*)  d_in[0];
    const float* emb  = (const float*)d_in[1];
    const float* Wih0 = (const float*)d_in[2];
    const float* Whh0 = (const float*)d_in[3];
    const float* bih0 = (const float*)d_in[4];
    const float* bhh0 = (const float*)d_in[5];
    const float* Wih1 = (const float*)d_in[6];
    const float* Whh1 = (const float*)d_in[7];
    const float* bih1 = (const float*)d_in[8];
    const float* bhh1 = (const float*)d_in[9];
    const float* W1   = (const float*)d_in[10];
    const float* b1   = (const float*)d_in[11];
    const float* W2   = (const float*)d_in[12];
    const float* b2   = (const float*)d_in[13];
    float* out = (float*)d_out;

    precompute_P0<<<VOCAB, 64>>>(emb, Wih0, bih0, bhh0);

    const int smem_bytes = (VOCAB * HID + 2 * TLEN + 512) * 4;  // 141,312 B
    cudaFuncSetAttribute(rnn_scan_kernel,
                         cudaFuncAttributeMaxDynamicSharedMemorySize, smem_bytes);
    rnn_scan_kernel<<<BATCH / 2, 128, smem_bytes>>>(
        x, Whh0, Wih1, Whh1, bih1, bhh1, W1, b1, W2, b2, out);
}